// round 15
// baseline (speedup 1.0000x reference)
#include <cuda_runtime.h>
#include <cstdint>

#define BB 8
#define NN 16384
#define FF 64
#define EE 262144
#define CC 10
#define BN_EPS 1e-5f

// ---------------- device scratch (no allocs; zero-initialized at load) ----------------
__device__ int    g_deg_out[BB * NN];
__device__ int    g_deg_in [BB * NN];
__device__ float  g_rs_out [BB * NN];
__device__ float  g_rs_in  [BB * NN];
__device__ int    g_row_off[BB * (NN + 1)];
__device__ int    g_epos   [(size_t)BB * EE];   // per-edge reserved slot within dst bucket
__device__ __align__(16) int   g_esrt[(size_t)BB * EE];
__device__ __align__(16) float g_xs [(size_t)BB * NN * FF];  // x * rs_out
__device__ __align__(16) float g_h1 [(size_t)BB * NN * FF];  // relu(conv1)*rs_out
__device__ __align__(16) float g_h2 [(size_t)BB * NN * FF];  // conv2 out
__device__ float  g_bn_sum [2 * FF];     // reset by k_bncoef each replay
__device__ float  g_bn_coef[2 * FF];

// ---------------- preprocessing ----------------

// degrees + in-bucket slot reservation (the deg_in atomic's return value IS the slot)
__global__ void k_degree(const int* __restrict__ src, const int* __restrict__ dst) {
    int i = blockIdx.x * blockDim.x + threadIdx.x;   // BB*EE = 2M
    int b = i >> 18;                                  // EE = 2^18
    int pos = atomicAdd(&g_deg_in[b * NN + dst[i]], 1);
    g_epos[i] = pos;
    atomicAdd(&g_deg_out[b * NN + src[i]], 1);
}

__global__ __launch_bounds__(1024) void k_scan() {
    __shared__ int warpsum[32];
    int b = blockIdx.x, t = threadIdx.x;
    int lane = t & 31, wid = t >> 5;
    int base = b * NN + t * 16;
    int loc[16];
    int sum = 0;
#pragma unroll
    for (int i = 0; i < 16; i++) {
        int d = g_deg_in[base + i];
        loc[i] = sum; sum += d;
        g_rs_in[base + i] = rsqrtf((float)(d < 1 ? 1 : d));
        int dgo = g_deg_out[base + i];
        g_rs_out[base + i] = rsqrtf((float)(dgo < 1 ? 1 : dgo));
        g_deg_in[base + i]  = 0;
        g_deg_out[base + i] = 0;
    }
    int v = sum;
#pragma unroll
    for (int off = 1; off < 32; off <<= 1) {
        int u = __shfl_up_sync(0xFFFFFFFFu, v, off);
        if (lane >= off) v += u;
    }
    if (lane == 31) warpsum[wid] = v;
    __syncthreads();
    if (wid == 0) {
        int w = warpsum[lane];
#pragma unroll
        for (int off = 1; off < 32; off <<= 1) {
            int u = __shfl_up_sync(0xFFFFFFFFu, w, off);
            if (lane >= off) w += u;
        }
        warpsum[lane] = w;
    }
    __syncthreads();
    int wbase = (wid == 0) ? 0 : warpsum[wid - 1];
    int excl  = wbase + v - sum;
    int ob = b * (NN + 1) + t * 16;
#pragma unroll
    for (int i = 0; i < 16; i++) g_row_off[ob + i] = excl + loc[i];
    if (t == 1023) g_row_off[b * (NN + 1) + NN] = excl + sum;
}

// atomic-free bucket-fill (slot precomputed) + prescale xs = x * rs_out
__global__ void k_fill(const int* __restrict__ src, const int* __restrict__ dst,
                       const float4* __restrict__ x4) {
    int i = blockIdx.x * blockDim.x + threadIdx.x;   // BB*EE == 2M
    int b = i >> 18;
    int s = src[i];
    int d = dst[i];
    int pos = g_epos[i];
    g_esrt[(size_t)b * EE + g_row_off[b * (NN + 1) + d] + pos] = s;

    float sc = g_rs_out[i >> 4];                      // (i*4)/FF
    float4 v = __ldg(x4 + i);
    v.x *= sc; v.y *= sc; v.z *= sc; v.w *= sc;
    ((float4*)g_xs)[i] = v;
}

// ---------------- fused conv: gather + GEMM (+ BN partials on phase 1) ----------------
// 512 threads, 32 nodes/CTA; regs clamped via __launch_bounds__(512, 4).
// Gather: 16 threads/node, one contiguous float4 each; writes TRANSPOSED swizzled
//         sT[k][node ^ s(k)], s(k)=2*((k>>4)&3) -> conflict-free scalar STS.
// GEMM:   threads 0..255, 2 nodes x 4 feats; x via ONE LDS.64 broadcast per k
//         (adjacent nodes in transposed layout) + LDS.128 w: 3 wf/warp/k vs 4.
// Phase 1 epilogue reduces per-feature sum/sumsq into g_bn_sum.

__global__ __launch_bounds__(512, 4) void k_conv(const float* __restrict__ W,
                                                 const float* __restrict__ bias,
                                                 int phase) {
    __shared__ float sW[64 * 64];
    __shared__ float sT[64][34];                      // [k][node], pad 34 (8B align + swizzle)
    __shared__ float sbn[8][128];

    const float* in  = phase ? g_h1 : g_xs;
    float*       out = phase ? g_h2 : g_h1;

    int t  = threadIdx.x;
    int cb = blockIdx.x;
    int b  = cb >> 9;                                 // 512 CTAs per batch
    int n0 = (cb & 511) << 5;

    for (int i = t; i < 64 * 64; i += 512) sW[i] = W[i];

    // ---- gather: 16 threads/node, 4 contiguous feats each ----
    {
        int nl = t >> 4;
        int f0 = (t & 15) << 2;
        int n  = n0 + nl;
        const float* inb = in + (size_t)b * NN * FF;
        const int*   es  = g_esrt + (size_t)b * EE;
        int r0 = g_row_off[b * (NN + 1) + n];
        int r1 = g_row_off[b * (NN + 1) + n + 1];

        float4 a = make_float4(0.f, 0.f, 0.f, 0.f);
        int e = r0;
        for (; e + 4 <= r1; e += 4) {
            int s0 = __ldg(es + e);
            int s1 = __ldg(es + e + 1);
            int s2 = __ldg(es + e + 2);
            int s3 = __ldg(es + e + 3);
            float4 v0 = __ldg((const float4*)(inb + (size_t)s0 * FF + f0));
            float4 v1 = __ldg((const float4*)(inb + (size_t)s1 * FF + f0));
            float4 v2 = __ldg((const float4*)(inb + (size_t)s2 * FF + f0));
            float4 v3 = __ldg((const float4*)(inb + (size_t)s3 * FF + f0));
            a.x += (v0.x + v1.x) + (v2.x + v3.x);
            a.y += (v0.y + v1.y) + (v2.y + v3.y);
            a.z += (v0.z + v1.z) + (v2.z + v3.z);
            a.w += (v0.w + v1.w) + (v2.w + v3.w);
        }
        for (; e < r1; e++) {
            int s0 = __ldg(es + e);
            float4 v0 = __ldg((const float4*)(inb + (size_t)s0 * FF + f0));
            a.x += v0.x; a.y += v0.y; a.z += v0.z; a.w += v0.w;
        }
        float si = g_rs_in[b * NN + n];
        int nls = nl ^ ((f0 >> 4) << 1);              // swizzle s(k), const for k=f0..f0+3
        sT[f0 + 0][nls] = a.x * si;
        sT[f0 + 1][nls] = a.y * si;
        sT[f0 + 2][nls] = a.z * si;
        sT[f0 + 3][nls] = a.w * si;
    }
    __syncthreads();

    // ---- GEMM (threads 0..255): 2 nodes x 4 feats, single LDS.64 x-broadcast per k ----
    if (t < 256) {
        int nn = (t >> 4) << 1;
        int q  = (t & 15) << 2;
        float4 c0 = make_float4(0.f, 0.f, 0.f, 0.f);
        float4 c1 = make_float4(0.f, 0.f, 0.f, 0.f);
#pragma unroll
        for (int kb = 0; kb < 4; kb++) {
            int nns = nn ^ (kb << 1);                 // matches s(k) for k in [16kb,16kb+16)
#pragma unroll
            for (int kk = 0; kk < 16; kk++) {
                int k = kb * 16 + kk;
                float2 x01 = *(const float2*)&sT[k][nns];
                float4 w = *(const float4*)&sW[k * 64 + q];
                c0.x = fmaf(x01.x, w.x, c0.x); c0.y = fmaf(x01.x, w.y, c0.y);
                c0.z = fmaf(x01.x, w.z, c0.z); c0.w = fmaf(x01.x, w.w, c0.w);
                c1.x = fmaf(x01.y, w.x, c1.x); c1.y = fmaf(x01.y, w.y, c1.y);
                c1.z = fmaf(x01.y, w.z, c1.z); c1.w = fmaf(x01.y, w.w, c1.w);
            }
        }
        float4 bv = __ldg((const float4*)(bias + q));
        c0.x += bv.x; c0.y += bv.y; c0.z += bv.z; c0.w += bv.w;
        c1.x += bv.x; c1.y += bv.y; c1.z += bv.z; c1.w += bv.w;
        int n = n0 + nn;
        if (phase == 0) {
            float s0 = __ldg(&g_rs_out[b * NN + n]);
            float s1 = __ldg(&g_rs_out[b * NN + n + 1]);
            c0.x = fmaxf(c0.x, 0.f) * s0; c0.y = fmaxf(c0.y, 0.f) * s0;
            c0.z = fmaxf(c0.z, 0.f) * s0; c0.w = fmaxf(c0.w, 0.f) * s0;
            c1.x = fmaxf(c1.x, 0.f) * s1; c1.y = fmaxf(c1.y, 0.f) * s1;
            c1.z = fmaxf(c1.z, 0.f) * s1; c1.w = fmaxf(c1.w, 0.f) * s1;
        }
        *(float4*)(out + ((size_t)b * NN + n)     * FF + q) = c0;
        *(float4*)(out + ((size_t)b * NN + n + 1) * FF + q) = c1;

        if (phase) {
            // BN partials: pair-reduce lane^16 (same q, other node pair)
            float s0 = c0.x + c1.x, s1 = c0.y + c1.y;
            float s2 = c0.z + c1.z, s3 = c0.w + c1.w;
            float q0s = c0.x * c0.x + c1.x * c1.x;
            float q1s = c0.y * c0.y + c1.y * c1.y;
            float q2s = c0.z * c0.z + c1.z * c1.z;
            float q3s = c0.w * c0.w + c1.w * c1.w;
            s0 += __shfl_xor_sync(0xFFFFFFFFu, s0, 16);
            s1 += __shfl_xor_sync(0xFFFFFFFFu, s1, 16);
            s2 += __shfl_xor_sync(0xFFFFFFFFu, s2, 16);
            s3 += __shfl_xor_sync(0xFFFFFFFFu, s3, 16);
            q0s += __shfl_xor_sync(0xFFFFFFFFu, q0s, 16);
            q1s += __shfl_xor_sync(0xFFFFFFFFu, q1s, 16);
            q2s += __shfl_xor_sync(0xFFFFFFFFu, q2s, 16);
            q3s += __shfl_xor_sync(0xFFFFFFFFu, q3s, 16);
            if ((t & 16) == 0) {                       // lanes 0-15 of each warp
                int w = t >> 5;
                sbn[w][q + 0] = s0; sbn[w][q + 1] = s1;
                sbn[w][q + 2] = s2; sbn[w][q + 3] = s3;
                sbn[w][64 + q + 0] = q0s; sbn[w][64 + q + 1] = q1s;
                sbn[w][64 + q + 2] = q2s; sbn[w][64 + q + 3] = q3s;
            }
        }
    }
    if (phase) {
        __syncthreads();
        if (t < 128) {
            float v = 0.f;
#pragma unroll
            for (int w = 0; w < 8; w++) v += sbn[w][t];
            atomicAdd(&g_bn_sum[t], v);
        }
    }
}

// ---------------- BN coef / final ----------------

__global__ void k_bncoef(const float* __restrict__ gamma, const float* __restrict__ beta,
                         const float* __restrict__ lin_b, float* __restrict__ out) {
    int t = threadIdx.x;
    if (t < 64) {
        const float inv_n = 1.0f / (float)(BB * NN);
        float s  = g_bn_sum[t];
        float s2 = g_bn_sum[64 + t];
        float mean = s * inv_n;
        float var  = s2 * inv_n - mean * mean;
        float scale = gamma[t] * rsqrtf(var + BN_EPS);
        g_bn_coef[t]      = scale;
        g_bn_coef[64 + t] = beta[t] - mean * scale;
        g_bn_sum[t] = 0.0f;
        g_bn_sum[64 + t] = 0.0f;
    }
    if (t < 80) out[t] = lin_b[t % CC];
}

__global__ __launch_bounds__(256) void k_final(const float* __restrict__ linW,
                                               float* __restrict__ out) {
    __shared__ float cf[128];
    if (threadIdx.x < 128) cf[threadIdx.x] = g_bn_coef[threadIdx.x];
    __syncthreads();

    int tid = blockIdx.x * 256 + threadIdx.x;
    int stride = gridDim.x * 256;
    const int NI4 = NN * FF / 4;
    float acc[BB][CC];
#pragma unroll
    for (int b = 0; b < BB; b++)
#pragma unroll
        for (int c = 0; c < CC; c++) acc[b][c] = 0.f;

    const float4* h4 = (const float4*)g_h2;
    const float4* w4 = (const float4*)linW;
    for (int i = tid; i < NI4; i += stride) {
        int f0 = (i & 15) * 4;
        float4 sc  = *(const float4*)&cf[f0];
        float4 sh4 = *(const float4*)&cf[64 + f0];
        float4 hv[BB];
#pragma unroll
        for (int b = 0; b < BB; b++) {
            float4 v = __ldg(h4 + (size_t)b * NI4 + i);
            hv[b].x = fmaf(v.x, sc.x, sh4.x);
            hv[b].y = fmaf(v.y, sc.y, sh4.y);
            hv[b].z = fmaf(v.z, sc.z, sh4.z);
            hv[b].w = fmaf(v.w, sc.w, sh4.w);
        }
#pragma unroll
        for (int c = 0; c < CC; c++) {
            float4 w = __ldg(w4 + (size_t)c * NI4 + i);
#pragma unroll
            for (int b = 0; b < BB; b++) {
                float t0 = fmaf(hv[b].x, w.x, hv[b].y * w.y);
                float t1 = fmaf(hv[b].z, w.z, hv[b].w * w.w);
                acc[b][c] += t0 + t1;
            }
        }
    }
#pragma unroll
    for (int b = 0; b < BB; b++)
#pragma unroll
        for (int c = 0; c < CC; c++)
#pragma unroll
            for (int off = 16; off > 0; off >>= 1)
                acc[b][c] += __shfl_xor_sync(0xFFFFFFFFu, acc[b][c], off);

    __shared__ float part[8][80];
    int w = threadIdx.x >> 5, lane = threadIdx.x & 31;
    if (lane == 0) {
#pragma unroll
        for (int b = 0; b < BB; b++)
#pragma unroll
            for (int c = 0; c < CC; c++) part[w][b * CC + c] = acc[b][c];
    }
    __syncthreads();
    int t = threadIdx.x;
    if (t < 80) {
        float s = 0.f;
#pragma unroll
        for (int ww = 0; ww < 8; ww++) s += part[ww][t];
        atomicAdd(&out[t], s);
    }
}

// ---------------- launch ----------------
extern "C" void kernel_launch(void* const* d_in, const int* in_sizes, int n_in,
                              void* d_out, int out_size) {
    const float* x     = (const float*)d_in[0];
    const int*   esrc  = (const int*)  d_in[1];
    const int*   edst  = (const int*)  d_in[2];
    const float* W1    = (const float*)d_in[3];
    const float* b1    = (const float*)d_in[4];
    const float* W2    = (const float*)d_in[5];
    const float* b2    = (const float*)d_in[6];
    const float* gamma = (const float*)d_in[7];
    const float* beta  = (const float*)d_in[8];
    const float* linW  = (const float*)d_in[9];
    const float* linb  = (const float*)d_in[10];
    float* out = (float*)d_out;

    k_degree <<<(BB * EE) / 256, 256>>>(esrc, edst);
    k_scan   <<<BB, 1024>>>();
    k_fill   <<<(BB * EE) / 256, 256>>>(esrc, edst, (const float4*)x);
    k_conv   <<<BB * (NN / 32), 512>>>(W1, b1, 0);   // idx 3 -> profiled
    k_conv   <<<BB * (NN / 32), 512>>>(W2, b2, 1);
    k_bncoef <<<1, 128>>>(gamma, beta, linb, out);
    k_final  <<<296, 256>>>(linW, out);
}

// round 16
// speedup vs baseline: 1.4368x; 1.4368x over previous
#include <cuda_runtime.h>
#include <cstdint>

#define BB 8
#define NN 16384
#define FF 64
#define EE 262144
#define CC 10
#define BN_EPS 1e-5f

// ---------------- device scratch (no allocs; zero-initialized at load) ----------------
__device__ int    g_deg_out[BB * NN];
__device__ int    g_deg_in [BB * NN];
__device__ float  g_rs_out [BB * NN];
__device__ float  g_rs_in  [BB * NN];
__device__ int    g_row_off[BB * (NN + 1)];
__device__ int    g_epos   [(size_t)BB * EE];   // per-edge reserved slot within dst bucket
__device__ __align__(16) int   g_esrt[(size_t)BB * EE];
__device__ __align__(16) float g_xs [(size_t)BB * NN * FF];  // x * rs_out
__device__ __align__(16) float g_h1 [(size_t)BB * NN * FF];  // relu(conv1)*rs_out
__device__ __align__(16) float g_h2 [(size_t)BB * NN * FF];  // conv2 out
__device__ float  g_bn_sum [2 * FF];     // reset by k_bncoef each replay
__device__ float  g_bn_coef[2 * FF];

// ---------------- preprocessing ----------------

// degrees + in-bucket slot reservation (the deg_in atomic's return value IS the slot)
__global__ void k_degree(const int* __restrict__ src, const int* __restrict__ dst) {
    int i = blockIdx.x * blockDim.x + threadIdx.x;   // BB*EE = 2M
    int b = i >> 18;                                  // EE = 2^18
    int pos = atomicAdd(&g_deg_in[b * NN + dst[i]], 1);
    g_epos[i] = pos;
    atomicAdd(&g_deg_out[b * NN + src[i]], 1);
}

__global__ __launch_bounds__(1024) void k_scan() {
    __shared__ int warpsum[32];
    int b = blockIdx.x, t = threadIdx.x;
    int lane = t & 31, wid = t >> 5;
    int base = b * NN + t * 16;
    int loc[16];
    int sum = 0;
#pragma unroll
    for (int i = 0; i < 16; i++) {
        int d = g_deg_in[base + i];
        loc[i] = sum; sum += d;
        g_rs_in[base + i] = rsqrtf((float)(d < 1 ? 1 : d));
        int dgo = g_deg_out[base + i];
        g_rs_out[base + i] = rsqrtf((float)(dgo < 1 ? 1 : dgo));
        g_deg_in[base + i]  = 0;
        g_deg_out[base + i] = 0;
    }
    int v = sum;
#pragma unroll
    for (int off = 1; off < 32; off <<= 1) {
        int u = __shfl_up_sync(0xFFFFFFFFu, v, off);
        if (lane >= off) v += u;
    }
    if (lane == 31) warpsum[wid] = v;
    __syncthreads();
    if (wid == 0) {
        int w = warpsum[lane];
#pragma unroll
        for (int off = 1; off < 32; off <<= 1) {
            int u = __shfl_up_sync(0xFFFFFFFFu, w, off);
            if (lane >= off) w += u;
        }
        warpsum[lane] = w;
    }
    __syncthreads();
    int wbase = (wid == 0) ? 0 : warpsum[wid - 1];
    int excl  = wbase + v - sum;
    int ob = b * (NN + 1) + t * 16;
#pragma unroll
    for (int i = 0; i < 16; i++) g_row_off[ob + i] = excl + loc[i];
    if (t == 1023) g_row_off[b * (NN + 1) + NN] = excl + sum;
}

// atomic-free bucket-fill (slot precomputed) + prescale xs = x * rs_out
__global__ void k_fill(const int* __restrict__ src, const int* __restrict__ dst,
                       const float4* __restrict__ x4) {
    int i = blockIdx.x * blockDim.x + threadIdx.x;   // BB*EE == 2M
    int b = i >> 18;
    int s = src[i];
    int d = dst[i];
    int pos = g_epos[i];
    g_esrt[(size_t)b * EE + g_row_off[b * (NN + 1) + d] + pos] = s;

    float sc = g_rs_out[i >> 4];                      // (i*4)/FF
    float4 v = __ldg(x4 + i);
    v.x *= sc; v.y *= sc; v.z *= sc; v.w *= sc;
    ((float4*)g_xs)[i] = v;
}

// ---------------- fused conv: gather + GEMM (+ BN partials on phase 1) ----------------
// EXACT R14 form (83.1us proven, regs=32, no spills). DO NOT MODIFY the hot loops.
// 512 threads, 32 nodes/CTA; regs clamped via __launch_bounds__(512, 4).
// Gather: 16 threads/node, one contiguous float4 each.
// GEMM:   threads 0..255, 2 nodes x 4 feats, per-k broadcast + LDS.128.
// Phase 1 epilogue reduces per-feature sum/sumsq into g_bn_sum.

__global__ __launch_bounds__(512, 4) void k_conv(const float* __restrict__ W,
                                                 const float* __restrict__ bias,
                                                 int phase) {
    __shared__ float sW[64 * 64];
    __shared__ float sT[32][68];
    __shared__ float sbn[8][128];

    const float* in  = phase ? g_h1 : g_xs;
    float*       out = phase ? g_h2 : g_h1;

    int t  = threadIdx.x;
    int cb = blockIdx.x;
    int b  = cb >> 9;                                 // 512 CTAs per batch
    int n0 = (cb & 511) << 5;

    for (int i = t; i < 64 * 64; i += 512) sW[i] = W[i];

    // ---- gather: 16 threads/node, 4 contiguous feats each ----
    {
        int nl = t >> 4;
        int f0 = (t & 15) << 2;
        int n  = n0 + nl;
        const float* inb = in + (size_t)b * NN * FF;
        const int*   es  = g_esrt + (size_t)b * EE;
        int r0 = g_row_off[b * (NN + 1) + n];
        int r1 = g_row_off[b * (NN + 1) + n + 1];

        float4 a = make_float4(0.f, 0.f, 0.f, 0.f);
        int e = r0;
        for (; e + 4 <= r1; e += 4) {
            int s0 = __ldg(es + e);
            int s1 = __ldg(es + e + 1);
            int s2 = __ldg(es + e + 2);
            int s3 = __ldg(es + e + 3);
            float4 v0 = __ldg((const float4*)(inb + (size_t)s0 * FF + f0));
            float4 v1 = __ldg((const float4*)(inb + (size_t)s1 * FF + f0));
            float4 v2 = __ldg((const float4*)(inb + (size_t)s2 * FF + f0));
            float4 v3 = __ldg((const float4*)(inb + (size_t)s3 * FF + f0));
            a.x += (v0.x + v1.x) + (v2.x + v3.x);
            a.y += (v0.y + v1.y) + (v2.y + v3.y);
            a.z += (v0.z + v1.z) + (v2.z + v3.z);
            a.w += (v0.w + v1.w) + (v2.w + v3.w);
        }
        for (; e < r1; e++) {
            int s0 = __ldg(es + e);
            float4 v0 = __ldg((const float4*)(inb + (size_t)s0 * FF + f0));
            a.x += v0.x; a.y += v0.y; a.z += v0.z; a.w += v0.w;
        }
        float si = g_rs_in[b * NN + n];
        float4 st;
        st.x = a.x * si; st.y = a.y * si; st.z = a.z * si; st.w = a.w * si;
        *(float4*)&sT[nl][f0] = st;
    }
    __syncthreads();

    // ---- GEMM (threads 0..255): 2 nodes x 4 feats, per-k (proven form) ----
    if (t < 256) {
        int nn = (t >> 4) << 1;
        int q  = (t & 15) << 2;
        float4 c0 = make_float4(0.f, 0.f, 0.f, 0.f);
        float4 c1 = make_float4(0.f, 0.f, 0.f, 0.f);
#pragma unroll
        for (int k = 0; k < 64; k++) {
            float x0 = sT[nn][k];
            float x1 = sT[nn + 1][k];
            float4 w = *(const float4*)&sW[k * 64 + q];
            c0.x = fmaf(x0, w.x, c0.x); c0.y = fmaf(x0, w.y, c0.y);
            c0.z = fmaf(x0, w.z, c0.z); c0.w = fmaf(x0, w.w, c0.w);
            c1.x = fmaf(x1, w.x, c1.x); c1.y = fmaf(x1, w.y, c1.y);
            c1.z = fmaf(x1, w.z, c1.z); c1.w = fmaf(x1, w.w, c1.w);
        }
        float4 bv = __ldg((const float4*)(bias + q));
        c0.x += bv.x; c0.y += bv.y; c0.z += bv.z; c0.w += bv.w;
        c1.x += bv.x; c1.y += bv.y; c1.z += bv.z; c1.w += bv.w;
        int n = n0 + nn;
        if (phase == 0) {
            float s0 = __ldg(&g_rs_out[b * NN + n]);
            float s1 = __ldg(&g_rs_out[b * NN + n + 1]);
            c0.x = fmaxf(c0.x, 0.f) * s0; c0.y = fmaxf(c0.y, 0.f) * s0;
            c0.z = fmaxf(c0.z, 0.f) * s0; c0.w = fmaxf(c0.w, 0.f) * s0;
            c1.x = fmaxf(c1.x, 0.f) * s1; c1.y = fmaxf(c1.y, 0.f) * s1;
            c1.z = fmaxf(c1.z, 0.f) * s1; c1.w = fmaxf(c1.w, 0.f) * s1;
        }
        *(float4*)(out + ((size_t)b * NN + n)     * FF + q) = c0;
        *(float4*)(out + ((size_t)b * NN + n + 1) * FF + q) = c1;

        if (phase) {
            // BN partials: pair-reduce lane^16 (same q, other node pair)
            float s0 = c0.x + c1.x, s1 = c0.y + c1.y;
            float s2 = c0.z + c1.z, s3 = c0.w + c1.w;
            float q0s = c0.x * c0.x + c1.x * c1.x;
            float q1s = c0.y * c0.y + c1.y * c1.y;
            float q2s = c0.z * c0.z + c1.z * c1.z;
            float q3s = c0.w * c0.w + c1.w * c1.w;
            s0 += __shfl_xor_sync(0xFFFFFFFFu, s0, 16);
            s1 += __shfl_xor_sync(0xFFFFFFFFu, s1, 16);
            s2 += __shfl_xor_sync(0xFFFFFFFFu, s2, 16);
            s3 += __shfl_xor_sync(0xFFFFFFFFu, s3, 16);
            q0s += __shfl_xor_sync(0xFFFFFFFFu, q0s, 16);
            q1s += __shfl_xor_sync(0xFFFFFFFFu, q1s, 16);
            q2s += __shfl_xor_sync(0xFFFFFFFFu, q2s, 16);
            q3s += __shfl_xor_sync(0xFFFFFFFFu, q3s, 16);
            if ((t & 16) == 0) {                       // lanes 0-15 of each warp
                int w = t >> 5;
                sbn[w][q + 0] = s0; sbn[w][q + 1] = s1;
                sbn[w][q + 2] = s2; sbn[w][q + 3] = s3;
                sbn[w][64 + q + 0] = q0s; sbn[w][64 + q + 1] = q1s;
                sbn[w][64 + q + 2] = q2s; sbn[w][64 + q + 3] = q3s;
            }
        }
    }
    if (phase) {
        __syncthreads();
        if (t < 128) {
            float v = 0.f;
#pragma unroll
            for (int w = 0; w < 8; w++) v += sbn[w][t];
            atomicAdd(&g_bn_sum[t], v);
        }
    }
}

// ---------------- BN coef / final ----------------

__global__ void k_bncoef(const float* __restrict__ gamma, const float* __restrict__ beta,
                         const float* __restrict__ lin_b, float* __restrict__ out) {
    int t = threadIdx.x;
    if (t < 64) {
        const float inv_n = 1.0f / (float)(BB * NN);
        float s  = g_bn_sum[t];
        float s2 = g_bn_sum[64 + t];
        float mean = s * inv_n;
        float var  = s2 * inv_n - mean * mean;
        float scale = gamma[t] * rsqrtf(var + BN_EPS);
        g_bn_coef[t]      = scale;
        g_bn_coef[64 + t] = beta[t] - mean * scale;
        g_bn_sum[t] = 0.0f;
        g_bn_sum[64 + t] = 0.0f;
    }
    if (t < 80) out[t] = lin_b[t % CC];
}

__global__ __launch_bounds__(256) void k_final(const float* __restrict__ linW,
                                               float* __restrict__ out) {
    __shared__ float cf[128];
    if (threadIdx.x < 128) cf[threadIdx.x] = g_bn_coef[threadIdx.x];
    __syncthreads();

    int tid = blockIdx.x * 256 + threadIdx.x;
    int stride = gridDim.x * 256;
    const int NI4 = NN * FF / 4;
    float acc[BB][CC];
#pragma unroll
    for (int b = 0; b < BB; b++)
#pragma unroll
        for (int c = 0; c < CC; c++) acc[b][c] = 0.f;

    const float4* h4 = (const float4*)g_h2;
    const float4* w4 = (const float4*)linW;
    for (int i = tid; i < NI4; i += stride) {
        int f0 = (i & 15) * 4;
        float4 sc  = *(const float4*)&cf[f0];
        float4 sh4 = *(const float4*)&cf[64 + f0];
        float4 hv[BB];
#pragma unroll
        for (int b = 0; b < BB; b++) {
            float4 v = __ldg(h4 + (size_t)b * NI4 + i);
            hv[b].x = fmaf(v.x, sc.x, sh4.x);
            hv[b].y = fmaf(v.y, sc.y, sh4.y);
            hv[b].z = fmaf(v.z, sc.z, sh4.z);
            hv[b].w = fmaf(v.w, sc.w, sh4.w);
        }
#pragma unroll
        for (int c = 0; c < CC; c++) {
            float4 w = __ldg(w4 + (size_t)c * NI4 + i);
#pragma unroll
            for (int b = 0; b < BB; b++) {
                float t0 = fmaf(hv[b].x, w.x, hv[b].y * w.y);
                float t1 = fmaf(hv[b].z, w.z, hv[b].w * w.w);
                acc[b][c] += t0 + t1;
            }
        }
    }
#pragma unroll
    for (int b = 0; b < BB; b++)
#pragma unroll
        for (int c = 0; c < CC; c++)
#pragma unroll
            for (int off = 16; off > 0; off >>= 1)
                acc[b][c] += __shfl_xor_sync(0xFFFFFFFFu, acc[b][c], off);

    __shared__ float part[8][80];
    int w = threadIdx.x >> 5, lane = threadIdx.x & 31;
    if (lane == 0) {
#pragma unroll
        for (int b = 0; b < BB; b++)
#pragma unroll
            for (int c = 0; c < CC; c++) part[w][b * CC + c] = acc[b][c];
    }
    __syncthreads();
    int t = threadIdx.x;
    if (t < 80) {
        float s = 0.f;
#pragma unroll
        for (int ww = 0; ww < 8; ww++) s += part[ww][t];
        atomicAdd(&out[t], s);
    }
}

// ---------------- launch ----------------
extern "C" void kernel_launch(void* const* d_in, const int* in_sizes, int n_in,
                              void* d_out, int out_size) {
    const float* x     = (const float*)d_in[0];
    const int*   esrc  = (const int*)  d_in[1];
    const int*   edst  = (const int*)  d_in[2];
    const float* W1    = (const float*)d_in[3];
    const float* b1    = (const float*)d_in[4];
    const float* W2    = (const float*)d_in[5];
    const float* b2    = (const float*)d_in[6];
    const float* gamma = (const float*)d_in[7];
    const float* beta  = (const float*)d_in[8];
    const float* linW  = (const float*)d_in[9];
    const float* linb  = (const float*)d_in[10];
    float* out = (float*)d_out;

    k_degree <<<(BB * EE) / 256, 256>>>(esrc, edst);
    k_scan   <<<BB, 1024>>>();
    k_fill   <<<(BB * EE) / 256, 256>>>(esrc, edst, (const float4*)x);
    k_conv   <<<BB * (NN / 32), 512>>>(W1, b1, 0);   // idx 3 -> profiled
    k_conv   <<<BB * (NN / 32), 512>>>(W2, b2, 1);
    k_bncoef <<<1, 128>>>(gamma, beta, linb, out);
    k_final  <<<296, 256>>>(linW, out);
}